// round 14
// baseline (speedup 1.0000x reference)
#include <cuda_runtime.h>
#include <math.h>

// ---------------------------------------------------------------------------
// GaussianSplattingCompliance: N_POINTS=131072, N_G=256
// s(z) = sigmoid(-10(z-1)).  Affine absorbs K=10*log2(e):
//   zp = sqrt(uu+vv) = K*z,  u = 2^(K - zp) = e^{-10(z-1)}  (always finite,
//   underflows to 0 for far gaussians),  s = u/(1+u)
// Quad identity (exact): with n=u0+u1+2*u0*u1, d=(1+u0)(1+u1):
//   s0+s1+s2+s3 = (n01*d23 + n23*d01) * rcp(d01*d23)
// MUFU per gaussian: sqrt(8) + ex2(8) + rcp/4(2) = 18 cyc (R7 tanh was 24).
// Main kernel: 2 threads/point (gaussian split), packed f32x2 affine math,
// straight-line scalar tail (no clamps, no predication).
// ---------------------------------------------------------------------------

#define N_POINTS 131072
#define N_G      256
#define PRE_BLOCKS 256
#define KK 14.4269504088896341f    // 10 * log2(e)

__device__ unsigned g_enc[4];
__device__ unsigned g_count;
__device__ float4   g_AB[N_G];     // A1,B1,A2,B2
__device__ float2   g_C[N_G];      // C1,C2

__device__ __forceinline__ unsigned f_enc(float f) {
    unsigned u = __float_as_uint(f);
    return (u & 0x80000000u) ? ~u : (u | 0x80000000u);
}
__device__ __forceinline__ float f_dec(unsigned e) {
    unsigned u = (e & 0x80000000u) ? (e ^ 0x80000000u) : ~e;
    return __uint_as_float(u);
}
__device__ __forceinline__ float sigmoid_f(float x) {
    return 1.0f / (1.0f + expf(-x));
}

// ---------------- fused prologue: minmax + params + scratch reset -----------
__global__ void __launch_bounds__(256)
gs_pre_kernel(const float4* __restrict__ coords4,
              const float*  __restrict__ W_scale,
              const float*  __restrict__ W_shape_var,
              const float*  __restrict__ W_rotation,
              const float2* __restrict__ W_offsets) {
    __shared__ float s_red[8][4];
    __shared__ int   s_last;
    int tid = threadIdx.x;

    float4 q = coords4[blockIdx.x * 256 + tid];
    float mxx = fmaxf(q.x, q.z), mxy = fmaxf(q.y, q.w);
    float nmx = -fminf(q.x, q.z), nmy = -fminf(q.y, q.w);

    #pragma unroll
    for (int o = 16; o > 0; o >>= 1) {
        mxx = fmaxf(mxx, __shfl_xor_sync(0xffffffffu, mxx, o));
        mxy = fmaxf(mxy, __shfl_xor_sync(0xffffffffu, mxy, o));
        nmx = fmaxf(nmx, __shfl_xor_sync(0xffffffffu, nmx, o));
        nmy = fmaxf(nmy, __shfl_xor_sync(0xffffffffu, nmy, o));
    }
    int wid = tid >> 5, lid = tid & 31;
    if (lid == 0) {
        s_red[wid][0] = mxx; s_red[wid][1] = mxy;
        s_red[wid][2] = nmx; s_red[wid][3] = nmy;
    }
    __syncthreads();
    if (tid == 0) {
        float a = s_red[0][0], b = s_red[0][1], c = s_red[0][2], d = s_red[0][3];
        #pragma unroll
        for (int w = 1; w < 8; w++) {
            a = fmaxf(a, s_red[w][0]); b = fmaxf(b, s_red[w][1]);
            c = fmaxf(c, s_red[w][2]); d = fmaxf(d, s_red[w][3]);
        }
        atomicMax(&g_enc[0], f_enc(a));
        atomicMax(&g_enc[1], f_enc(b));
        atomicMax(&g_enc[2], f_enc(c));
        atomicMax(&g_enc[3], f_enc(d));
        __threadfence();
        unsigned done = atomicAdd(&g_count, 1u);
        s_last = (done == PRE_BLOCKS - 1) ? 1 : 0;
    }
    __syncthreads();
    if (!s_last) return;

    float cmaxx = f_dec(atomicMax(&g_enc[0], 0u));
    float cmaxy = f_dec(atomicMax(&g_enc[1], 0u));
    float cminx = -f_dec(atomicMax(&g_enc[2], 0u));
    float cminy = -f_dec(atomicMax(&g_enc[3], 0u));

    float lo_x = cminx - cmaxx * 0.05f, hi_x = cmaxx + cmaxx * 0.05f;
    float lo_y = cminy - cmaxy * 0.05f, hi_y = cmaxy + cmaxy * 0.05f;

    int b = tid;
    float base_scale = (1.5f - 0.05f) * sigmoid_f(W_scale[b]) + 0.05f;
    float ratio      = (3.5f - 0.5f) * sigmoid_f(W_shape_var[b]) + 0.5f;
    const float PI_F = 3.14159265358979323846f;
    float rot        = -0.5f * PI_F + PI_F * sigmoid_f(W_rotation[b]);
    float2 wo = W_offsets[b];
    float ox = lo_x + (hi_x - lo_x) * sigmoid_f(wo.x);
    float oy = lo_y + (hi_y - lo_y) * sigmoid_f(wo.y);

    float inv_s = 1.0f / (base_scale + 1e-8f);
    float sq0 = sqrtf(1.0f / (1.0f + 1e-6f));
    float sq1 = sqrtf(1.0f / (ratio * ratio + 1e-6f));
    float c = cosf(rot), s = sinf(rot);

    float k0 = KK * inv_s * sq0;     // absorb K = 10*log2(e)
    float k1 = KK * inv_s * sq1;
    float A1 =  c * k0, B1 = -s * k0;
    float A2 =  s * k1, B2 =  c * k1;
    float C1 = -(A1 * ox + B1 * oy);
    float C2 = -(A2 * ox + B2 * oy);

    g_AB[b] = make_float4(A1, B1, A2, B2);
    g_C[b]  = make_float2(C1, C2);

    if (tid < 4) g_enc[tid] = 0u;
    if (tid == 0) g_count = 0u;
}

// ------- main kernel: 2 threads/point (split gaussians), f32x2 affine -------

#define FMA2(d, a, b, c) \
    asm("fma.rn.f32x2 %0, %1, %2, %3;" : "=l"(d) : "l"(a), "l"(b), "l"(c))
#define MUL2(d, a, b) \
    asm("mul.rn.f32x2 %0, %1, %2;" : "=l"(d) : "l"(a), "l"(b))
#define PACK2(d, lo, hi) \
    asm("mov.b64 %0, {%1, %2};" : "=l"(d) : "f"(lo), "f"(hi))
#define UNPACK2(lo, hi, s) \
    asm("mov.b64 {%0, %1}, %2;" : "=f"(lo), "=f"(hi) : "l"(s))

#define N_PAIR   (N_G / 2)      // 128 gaussian pairs
#define PTS_BLK  128            // points per block
#define HALF_GP  (N_PAIR / 2)   // 64 pairs per thread-half
#define HALF_QD  (HALF_GP / 2)  // 32 quads (4 gaussians) per thread-half

__device__ __forceinline__ float sqrt_ap(float x) {
    float r; asm("sqrt.approx.f32 %0, %1;" : "=f"(r) : "f"(x)); return r;
}
__device__ __forceinline__ float ex2_ap(float x) {
    float r; asm("ex2.approx.f32 %0, %1;" : "=f"(r) : "f"(x)); return r;
}
__device__ __forceinline__ float rcp_ap(float x) {
    float r; asm("rcp.approx.f32 %0, %1;" : "=f"(r) : "f"(x)); return r;
}

__global__ void __launch_bounds__(256)
gs_main_kernel(const float2* __restrict__ coords, float* __restrict__ out) {
    // per gaussian PAIR p (gaussians 2p, 2p+1), 3 x 16B entries:
    //   sP[3p+0] = {A1_e, A1_o, B1_e, B1_o}
    //   sP[3p+1] = {A2_e, A2_o, B2_e, B2_o}
    //   sP[3p+2] = {C1_e, C1_o, C2_e, C2_o}
    __shared__ ulonglong2 sP[N_PAIR * 3];
    __shared__ float s_part[PTS_BLK];
    int t = threadIdx.x;

    if (t < N_PAIR) {
        float4 abE = g_AB[2 * t];
        float4 abO = g_AB[2 * t + 1];
        float2 cE  = g_C[2 * t];
        float2 cO  = g_C[2 * t + 1];
        float4* dst = (float4*)&sP[3 * t];
        dst[0] = make_float4(abE.x, abO.x, abE.y, abO.y);
        dst[1] = make_float4(abE.z, abO.z, abE.w, abO.w);
        dst[2] = make_float4(cE.x,  cO.x,  cE.y,  cO.y);
    }
    __syncthreads();

    int half = t >> 7;                    // 0: pairs 0..63, 1: pairs 64..127
    int tp   = t & (PTS_BLK - 1);
    int i = blockIdx.x * PTS_BLK + tp;
    float2 p = coords[i];
    unsigned long long cxx, cyy;
    PACK2(cxx, p.x, p.x);
    PACK2(cyy, p.y, p.y);

    const ulonglong2* pp = &sP[half * HALF_GP * 3];
    float sum = 0.0f;
    #pragma unroll 4
    for (int q = 0; q < HALF_QD; q++) {   // 4 gaussians (2 packed pairs)/iter
        ulonglong2 qa0 = pp[6 * q + 0];
        ulonglong2 qa1 = pp[6 * q + 1];
        ulonglong2 qa2 = pp[6 * q + 2];
        ulonglong2 qb0 = pp[6 * q + 3];
        ulonglong2 qb1 = pp[6 * q + 4];
        ulonglong2 qb2 = pp[6 * q + 5];

        unsigned long long uA, vA, ssA, tA, uB, vB, ssB, tB;
        FMA2(tA, qa0.y, cyy, qa2.x);
        FMA2(uA, qa0.x, cxx, tA);
        FMA2(tA, qa1.y, cyy, qa2.y);
        FMA2(vA, qa1.x, cxx, tA);
        MUL2(tA, vA, vA);
        FMA2(ssA, uA, uA, tA);            // {K^2 z^2} gaussians 0,1

        FMA2(tB, qb0.y, cyy, qb2.x);
        FMA2(uB, qb0.x, cxx, tB);
        FMA2(tB, qb1.y, cyy, qb2.y);
        FMA2(vB, qb1.x, cxx, tB);
        MUL2(tB, vB, vB);
        FMA2(ssB, uB, uB, tB);            // {K^2 z^2} gaussians 2,3

        float s0, s1, s2, s3;
        UNPACK2(s0, s1, ssA);
        UNPACK2(s2, s3, ssB);

        // u_i = 2^(K - K*z_i) = e^{-10(z_i-1)}   (finite: <= 2^14.43)
        float u0 = ex2_ap(KK - sqrt_ap(s0));
        float u1 = ex2_ap(KK - sqrt_ap(s1));
        float u2 = ex2_ap(KK - sqrt_ap(s2));
        float u3 = ex2_ap(KK - sqrt_ap(s3));

        // s0+s1 = n01/d01, n = a+2P, d = (1+a)+P, a = u0+u1, P = u0*u1
        float a01 = u0 + u1;
        float P01 = u0 * u1;
        float n01 = fmaf(2.0f, P01, a01);
        float d01 = (a01 + 1.0f) + P01;

        float a23 = u2 + u3;
        float P23 = u2 * u3;
        float n23 = fmaf(2.0f, P23, a23);
        float d23 = (a23 + 1.0f) + P23;

        // quad combine: one rcp for 4 gaussians (exact identity)
        float NUM = fmaf(n01, d23, n23 * d01);
        float DEN = d01 * d23;
        sum = fmaf(NUM, rcp_ap(DEN), sum);
    }

    if (half) s_part[tp] = sum;
    __syncthreads();
    if (!half) {
        float tot = sum + s_part[tp];     // sum of s over all 256 gaussians
        float ks = tot + 1e-8f;
        float e = __expf(10.0f * (ks - 0.5f));
        out[i] = (1.0f - 1e-9f) / (1.0f + e) + 1e-9f;
    }
}

extern "C" void kernel_launch(void* const* d_in, const int* in_sizes, int n_in,
                              void* d_out, int out_size) {
    const float4* coords4     = (const float4*)d_in[0];
    const float2* coords2     = (const float2*)d_in[0];
    const float*  W_scale     = (const float*)d_in[1];
    const float*  W_shape_var = (const float*)d_in[2];
    const float*  W_rotation  = (const float*)d_in[3];
    const float2* W_offsets   = (const float2*)d_in[4];
    float* out = (float*)d_out;

    gs_pre_kernel<<<PRE_BLOCKS, 256>>>(coords4, W_scale, W_shape_var,
                                       W_rotation, W_offsets);
    gs_main_kernel<<<N_POINTS / PTS_BLK, 256>>>(coords2, out);
}

// round 17
// speedup vs baseline: 2.2097x; 2.2097x over previous
#include <cuda_runtime.h>
#include <math.h>

// ---------------------------------------------------------------------------
// GaussianSplattingCompliance: N_POINTS=131072, N_G=256
//   kernel = sigmoid(-10(z-1)) = 0.5 - 0.5*tanh(5(z-1))
// Affine precompute absorbs slope 5: sqrt(uu+vv) == 5z.
// Early-exit: H saturates to EMIN once ks > ~4; each half's partial ks is a
// lower bound on total ks, so once a warp's every lane has partial > 6 the
// remaining gaussians cannot change H (abs err <= sigmoid(-55) ~ 1e-24).
// Main kernel: 2 threads/point (gaussian split), 4 chunks x 16 pairs, vote.
// ---------------------------------------------------------------------------

#define N_POINTS 131072
#define N_G      256
#define PRE_BLOCKS 256

__device__ unsigned g_enc[4];      // enc(max x), enc(max y), enc(max -x), enc(max -y)
__device__ unsigned g_count;
__device__ float4   g_AB[N_G];     // A1,B1,A2,B2
__device__ float2   g_C[N_G];      // C1,C2

__device__ __forceinline__ unsigned f_enc(float f) {
    unsigned u = __float_as_uint(f);
    return (u & 0x80000000u) ? ~u : (u | 0x80000000u);
}
__device__ __forceinline__ float f_dec(unsigned e) {
    unsigned u = (e & 0x80000000u) ? (e ^ 0x80000000u) : ~e;
    return __uint_as_float(u);
}
__device__ __forceinline__ float sigmoid_f(float x) {
    return 1.0f / (1.0f + expf(-x));
}

// ---------------- fused prologue: minmax + params + scratch reset -----------
__global__ void __launch_bounds__(256)
gs_pre_kernel(const float4* __restrict__ coords4,
              const float*  __restrict__ W_scale,
              const float*  __restrict__ W_shape_var,
              const float*  __restrict__ W_rotation,
              const float2* __restrict__ W_offsets) {
    __shared__ float s_red[8][4];
    __shared__ int   s_last;
    int tid = threadIdx.x;

    float4 q = coords4[blockIdx.x * 256 + tid];
    float mxx = fmaxf(q.x, q.z), mxy = fmaxf(q.y, q.w);
    float nmx = -fminf(q.x, q.z), nmy = -fminf(q.y, q.w);

    #pragma unroll
    for (int o = 16; o > 0; o >>= 1) {
        mxx = fmaxf(mxx, __shfl_xor_sync(0xffffffffu, mxx, o));
        mxy = fmaxf(mxy, __shfl_xor_sync(0xffffffffu, mxy, o));
        nmx = fmaxf(nmx, __shfl_xor_sync(0xffffffffu, nmx, o));
        nmy = fmaxf(nmy, __shfl_xor_sync(0xffffffffu, nmy, o));
    }
    int wid = tid >> 5, lid = tid & 31;
    if (lid == 0) {
        s_red[wid][0] = mxx; s_red[wid][1] = mxy;
        s_red[wid][2] = nmx; s_red[wid][3] = nmy;
    }
    __syncthreads();
    if (tid == 0) {
        float a = s_red[0][0], b = s_red[0][1], c = s_red[0][2], d = s_red[0][3];
        #pragma unroll
        for (int w = 1; w < 8; w++) {
            a = fmaxf(a, s_red[w][0]); b = fmaxf(b, s_red[w][1]);
            c = fmaxf(c, s_red[w][2]); d = fmaxf(d, s_red[w][3]);
        }
        atomicMax(&g_enc[0], f_enc(a));
        atomicMax(&g_enc[1], f_enc(b));
        atomicMax(&g_enc[2], f_enc(c));
        atomicMax(&g_enc[3], f_enc(d));
        __threadfence();
        unsigned done = atomicAdd(&g_count, 1u);
        s_last = (done == PRE_BLOCKS - 1) ? 1 : 0;
    }
    __syncthreads();
    if (!s_last) return;

    float cmaxx = f_dec(atomicMax(&g_enc[0], 0u));
    float cmaxy = f_dec(atomicMax(&g_enc[1], 0u));
    float cminx = -f_dec(atomicMax(&g_enc[2], 0u));
    float cminy = -f_dec(atomicMax(&g_enc[3], 0u));

    float lo_x = cminx - cmaxx * 0.05f, hi_x = cmaxx + cmaxx * 0.05f;
    float lo_y = cminy - cmaxy * 0.05f, hi_y = cmaxy + cmaxy * 0.05f;

    int b = tid;
    float base_scale = (1.5f - 0.05f) * sigmoid_f(W_scale[b]) + 0.05f;
    float ratio      = (3.5f - 0.5f) * sigmoid_f(W_shape_var[b]) + 0.5f;
    const float PI_F = 3.14159265358979323846f;
    float rot        = -0.5f * PI_F + PI_F * sigmoid_f(W_rotation[b]);
    float2 wo = W_offsets[b];
    float ox = lo_x + (hi_x - lo_x) * sigmoid_f(wo.x);
    float oy = lo_y + (hi_y - lo_y) * sigmoid_f(wo.y);

    float inv_s = 1.0f / (base_scale + 1e-8f);
    float sq0 = sqrtf(1.0f / (1.0f + 1e-6f));
    float sq1 = sqrtf(1.0f / (ratio * ratio + 1e-6f));
    float c = cosf(rot), s = sinf(rot);

    float k0 = 5.0f * inv_s * sq0;        // absorb tanh slope 5
    float k1 = 5.0f * inv_s * sq1;
    float A1 =  c * k0, B1 = -s * k0;
    float A2 =  s * k1, B2 =  c * k1;
    float C1 = -(A1 * ox + B1 * oy);
    float C2 = -(A2 * ox + B2 * oy);

    g_AB[b] = make_float4(A1, B1, A2, B2);
    g_C[b]  = make_float2(C1, C2);

    if (tid < 4) g_enc[tid] = 0u;
    if (tid == 0) g_count = 0u;
}

// ------- main kernel: 2 threads/point, chunked with saturation vote ---------

#define FMA2(d, a, b, c) \
    asm("fma.rn.f32x2 %0, %1, %2, %3;" : "=l"(d) : "l"(a), "l"(b), "l"(c))
#define MUL2(d, a, b) \
    asm("mul.rn.f32x2 %0, %1, %2;" : "=l"(d) : "l"(a), "l"(b))
#define PACK2(d, lo, hi) \
    asm("mov.b64 %0, {%1, %2};" : "=l"(d) : "f"(lo), "f"(hi))
#define UNPACK2(lo, hi, s) \
    asm("mov.b64 {%0, %1}, %2;" : "=f"(lo), "=f"(hi) : "l"(s))

#define N_PAIR    (N_G / 2)      // 128 gaussian pairs
#define PTS_BLK   128            // points per block
#define HALF_GP   (N_PAIR / 2)   // 64 pairs per thread-half
#define CHUNK_GP  16             // pairs per chunk (32 gaussians)
#define N_CHUNK   (HALF_GP / CHUNK_GP)   // 4

__global__ void __launch_bounds__(256)
gs_main_kernel(const float2* __restrict__ coords, float* __restrict__ out) {
    // per gaussian PAIR p (gaussians 2p, 2p+1), 3 x 16B entries:
    //   sP[3p+0] = {A1_e, A1_o, B1_e, B1_o}
    //   sP[3p+1] = {A2_e, A2_o, B2_e, B2_o}
    //   sP[3p+2] = {C1_e, C1_o, C2_e, C2_o}
    __shared__ ulonglong2 sP[N_PAIR * 3];
    __shared__ float s_part[PTS_BLK];
    int t = threadIdx.x;

    if (t < N_PAIR) {
        float4 abE = g_AB[2 * t];
        float4 abO = g_AB[2 * t + 1];
        float2 cE  = g_C[2 * t];
        float2 cO  = g_C[2 * t + 1];
        float4* dst = (float4*)&sP[3 * t];
        dst[0] = make_float4(abE.x, abO.x, abE.y, abO.y);   // A1 pair, B1 pair
        dst[1] = make_float4(abE.z, abO.z, abE.w, abO.w);   // A2 pair, B2 pair
        dst[2] = make_float4(cE.x,  cO.x,  cE.y,  cO.y);    // C1 pair, C2 pair
    }
    __syncthreads();

    int half = t >> 7;                    // 0: pairs 0..63, 1: pairs 64..127
    int tp   = t & (PTS_BLK - 1);         // point slot within block
    int i = blockIdx.x * PTS_BLK + tp;
    float2 p = coords[i];
    unsigned long long cxx, cyy;
    PACK2(cxx, p.x, p.x);
    PACK2(cyy, p.y, p.y);

    const ulonglong2* pp = &sP[half * HALF_GP * 3];
    float sum0 = 0.0f, sum1 = 0.0f;       // tanh accumulators (even/odd)
    int cdone = N_CHUNK;

    for (int c = 0; c < N_CHUNK; c++) {
        #pragma unroll
        for (int k = 0; k < CHUNK_GP; k++) {
            int gp = c * CHUNK_GP + k;
            ulonglong2 q0 = pp[3 * gp + 0];   // {A1 pair, B1 pair}
            ulonglong2 q1 = pp[3 * gp + 1];   // {A2 pair, B2 pair}
            ulonglong2 q2 = pp[3 * gp + 2];   // {C1 pair, C2 pair}
            unsigned long long uu, vv, ss, t1;
            FMA2(t1, q0.y, cyy, q2.x);
            FMA2(uu, q0.x, cxx, t1);
            FMA2(t1, q1.y, cyy, q2.y);
            FMA2(vv, q1.x, cxx, t1);
            MUL2(t1, vv, vv);
            FMA2(ss, uu, uu, t1);             // {(5z)^2 even, odd}

            float s0, s1;
            UNPACK2(s0, s1, ss);
            float zp0, zp1, th0, th1;
            asm("sqrt.approx.f32 %0, %1;" : "=f"(zp0) : "f"(s0));
            asm("sqrt.approx.f32 %0, %1;" : "=f"(zp1) : "f"(s1));
            asm("tanh.approx.f32 %0, %1;" : "=f"(th0) : "f"(zp0 - 5.0f));
            asm("tanh.approx.f32 %0, %1;" : "=f"(th1) : "f"(zp1 - 5.0f));
            sum0 += th0;
            sum1 += th1;
        }
        if (c < N_CHUNK - 1) {
            // partial ks for this half: 32*(c+1) gaussians processed,
            // s = 0.5 - 0.5*t each -> partial = 16*(c+1) - 0.5*(sum0+sum1).
            // Lower bound on total ks; once > 6 for the whole warp, H is
            // pinned at EMIN (abs err <= sigmoid(-55)).
            float part = fmaf(-0.5f, sum0 + sum1, 16.0f * (float)(c + 1));
            if (__all_sync(0xffffffffu, part > 6.0f)) { cdone = c + 1; break; }
        }
    }

    // s-sum over the gaussians this half actually processed
    float s_half = fmaf(-0.5f, sum0 + sum1, 16.0f * (float)cdone);
    if (half) s_part[tp] = s_half;
    __syncthreads();
    if (!half) {
        float ks = (s_half + s_part[tp]) + 1e-8f;
        float e = __expf(10.0f * (ks - 0.5f));
        out[i] = (1.0f - 1e-9f) / (1.0f + e) + 1e-9f;
    }
}

extern "C" void kernel_launch(void* const* d_in, const int* in_sizes, int n_in,
                              void* d_out, int out_size) {
    const float4* coords4     = (const float4*)d_in[0];
    const float2* coords2     = (const float2*)d_in[0];
    const float*  W_scale     = (const float*)d_in[1];
    const float*  W_shape_var = (const float*)d_in[2];
    const float*  W_rotation  = (const float*)d_in[3];
    const float2* W_offsets   = (const float2*)d_in[4];
    float* out = (float*)d_out;

    gs_pre_kernel<<<PRE_BLOCKS, 256>>>(coords4, W_scale, W_shape_var,
                                       W_rotation, W_offsets);
    gs_main_kernel<<<N_POINTS / PTS_BLK, 256>>>(coords2, out);
}